// round 1
// baseline (speedup 1.0000x reference)
#include <cuda_runtime.h>
#include <cstdint>

#define DIMS 64
#define SVOL (64*64*64)          // 262144 voxels per volume
#define NBATCH 4
#define NCLASS 4
#define NPAIR 12                 // B * (C-1)
#define NVOL 24                  // NPAIR * 2 (out/in seeds)
#define NTOT (NBATCH*SVOL)       // 1048576
#define INF_SENT 1e12f
#define SMOOTHV 1e-5f

// ---- scratch (static device globals; no runtime allocation) ----
__device__ float g_F[(size_t)NVOL * SVOL];      // ~25 MB distance fields
__device__ float g_prob[(size_t)NPAIR * SVOL];  // ~12.6 MB probs for classes 1..3
__device__ float g_TP[16];
__device__ float g_PS[16];
__device__ float g_CNT[16];
__device__ float g_focal;
__device__ float g_bsum[NPAIR];
__device__ int   g_flag64;

// ============================================================
// K0: zero accumulators + detect whether targets buffer is int64
// (odd 32-bit words all zero => little-endian int64 with values 0..3)
// ============================================================
__global__ void k0_init(const int* __restrict__ tgt32) {
    int t = threadIdx.x;
    __shared__ int any;
    if (t == 0) any = 0;
    __syncthreads();
    int v = tgt32[2 * t + 1];   // words 1,3,...,511 -> within 2KB, safe either way
    if (v != 0) atomicOr(&any, 1);
    __syncthreads();
    if (t == 0) g_flag64 = (any == 0) ? 1 : 0;
    if (t < 16) { g_TP[t] = 0.f; g_PS[t] = 0.f; g_CNT[t] = 0.f; }
    if (t < NPAIR) g_bsum[t] = 0.f;
    if (t == 0) g_focal = 0.f;
}

// nearest set-bit squared distance within a 64-bit line mask
__device__ __forceinline__ float nd2(unsigned long long M, int i) {
    if (M == 0ULL) return INF_SENT;
    unsigned long long L = M << (63 - i);        // bit i -> position 63
    int dl = L ? __clzll((long long)L) : 9999;
    unsigned long long R = M >> i;
    int dr = R ? (__ffsll((long long)R) - 1) : 9999;
    int d = min(dl, dr);
    return (float)(d * d);
}

// ============================================================
// K1: per-voxel softmax, focal, Tversky partial sums, prob store,
//     and EDT pass-1 along W via ballot bitmasks (seeds for 6 volumes/voxel)
// ============================================================
__global__ void __launch_bounds__(256) k1_main(const float* __restrict__ preds,
                                               const int* __restrict__ tgt32) {
    const int tid = threadIdx.x;
    const int g = blockIdx.x * 256 + tid;
    const int b = g >> 18;           // / SVOL
    const int s = g & (SVOL - 1);

    const int f64 = g_flag64;
    const int t = tgt32[f64 ? (g << 1) : g];

    const float x0 = preds[(size_t)(b * 4 + 0) * SVOL + s];
    const float x1 = preds[(size_t)(b * 4 + 1) * SVOL + s];
    const float x2 = preds[(size_t)(b * 4 + 2) * SVOL + s];
    const float x3 = preds[(size_t)(b * 4 + 3) * SVOL + s];

    const float m  = fmaxf(fmaxf(x0, x1), fmaxf(x2, x3));
    const float e0 = expf(x0 - m), e1 = expf(x1 - m);
    const float e2 = expf(x2 - m), e3 = expf(x3 - m);
    const float se = e0 + e1 + e2 + e3;
    const float inv = 1.0f / se;
    const float p0 = e0 * inv, p1 = e1 * inv, p2 = e2 * inv, p3 = e3 * inv;

    const float xt = (t == 0) ? x0 : (t == 1) ? x1 : (t == 2) ? x2 : x3;
    const float ce = -(xt - m - logf(se));
    const float pt = expf(-ce);
    const float om = 1.0f - pt;
    const float focal = om * om * ce;

    // store probs for classes 1..3 (needed by boundary term)
    g_prob[(size_t)(b * 3 + 0) * SVOL + s] = p1;
    g_prob[(size_t)(b * 3 + 1) * SVOL + s] = p2;
    g_prob[(size_t)(b * 3 + 2) * SVOL + s] = p3;

    // ---- EDT pass-1 along W via line bitmasks ----
    const unsigned full = 0xFFFFFFFFu;
    const unsigned bal1 = __ballot_sync(full, t == 1);
    const unsigned bal2 = __ballot_sync(full, t == 2);
    const unsigned bal3 = __ballot_sync(full, t == 3);
    __shared__ unsigned sb[3][8];
    const int wid = tid >> 5;
    if ((tid & 31) == 0) { sb[0][wid] = bal1; sb[1][wid] = bal2; sb[2][wid] = bal3; }
    __syncthreads();

    const int line = tid >> 6;   // 0..3 within block
    const int i = tid & 63;      // position in line (== w)
#pragma unroll
    for (int cm = 0; cm < 3; cm++) {
        unsigned long long M = (unsigned long long)sb[cm][line * 2] |
                               ((unsigned long long)sb[cm][line * 2 + 1] << 32);
        const int v = (b * 3 + cm) * 2;
        g_F[(size_t)v * SVOL + s]       = nd2(M, i);    // seeds = mask
        g_F[(size_t)(v + 1) * SVOL + s] = nd2(~M, i);   // seeds = ~mask
    }

    // ---- block reduce 13 quantities, then atomic ----
    float vals[13];
    vals[0] = (t == 0) ? p0 : 0.f;
    vals[1] = (t == 1) ? p1 : 0.f;
    vals[2] = (t == 2) ? p2 : 0.f;
    vals[3] = (t == 3) ? p3 : 0.f;
    vals[4] = p0; vals[5] = p1; vals[6] = p2; vals[7] = p3;
    vals[8]  = (t == 0) ? 1.f : 0.f;
    vals[9]  = (t == 1) ? 1.f : 0.f;
    vals[10] = (t == 2) ? 1.f : 0.f;
    vals[11] = (t == 3) ? 1.f : 0.f;
    vals[12] = focal;

    __shared__ float red[13 * 8];
#pragma unroll
    for (int q = 0; q < 13; q++) {
        float v = vals[q];
#pragma unroll
        for (int o = 16; o > 0; o >>= 1) v += __shfl_down_sync(full, v, o);
        if ((tid & 31) == 0) red[q * 8 + wid] = v;
    }
    __syncthreads();
    if (tid < 13) {
        float sum = 0.f;
#pragma unroll
        for (int k = 0; k < 8; k++) sum += red[tid * 8 + k];
        if (tid < 4)       atomicAdd(&g_TP[b * 4 + tid], sum);
        else if (tid < 8)  atomicAdd(&g_PS[b * 4 + tid - 4], sum);
        else if (tid < 12) atomicAdd(&g_CNT[b * 4 + tid - 8], sum);
        else               atomicAdd(&g_focal, sum);
    }
}

// ============================================================
// K2: EDT pass along H, in-place per (volume, d)-slice.
// Tile 64x64 in SMEM; thread owns column w and 16 interleaved rows.
// ============================================================
__global__ void __launch_bounds__(256) k2_passH() {
    __shared__ float T[4096];
    const int v = blockIdx.x >> 6;
    const int d = blockIdx.x & 63;
    const size_t base = (size_t)v * SVOL + (size_t)d * 4096;
    const int tid = threadIdx.x;

#pragma unroll
    for (int r = 0; r < 16; r++) T[tid + r * 256] = g_F[base + tid + r * 256];
    __syncthreads();

    const int w = tid & 63;
    const int gq = tid >> 6;           // row group 0..3; rows i = gq + 4k
    float acc[16], dk[16];
#pragma unroll
    for (int k = 0; k < 16; k++) { acc[k] = 3.0e38f; dk[k] = (float)(gq + 4 * k); }

    for (int j = 0; j < 64; j++) {
        const float fj = T[j * 64 + w];
#pragma unroll
        for (int k = 0; k < 16; k++) {
            acc[k] = fminf(acc[k], fmaf(dk[k], dk[k], fj));
            dk[k] -= 1.0f;
        }
    }
#pragma unroll
    for (int k = 0; k < 16; k++) g_F[base + (size_t)(gq + 4 * k) * 64 + w] = acc[k];
}

// ============================================================
// K3: EDT pass along D for the (out,in) pair + sdf = sqrt(out)-sqrt(in),
//     contrib = sum(sdf * prob) accumulated per (b, class)
// ============================================================
__global__ void __launch_bounds__(256) k3_passD() {
    __shared__ float T[4096];
    __shared__ float red[8];
    const int p = blockIdx.x >> 6;   // pair index (b*3+cm)
    const int h = blockIdx.x & 63;
    const int tid = threadIdx.x;
    const int w = tid & 63;
    const int gq = tid >> 6;
    const size_t baseO = (size_t)(2 * p) * SVOL + (size_t)h * 64;
    const size_t baseI = baseO + SVOL;

    // ---- transform OUT volume ----
#pragma unroll
    for (int r = 0; r < 16; r++) {
        int idx = tid + r * 256;
        T[idx] = g_F[baseO + (size_t)(idx >> 6) * 4096 + (idx & 63)];
    }
    __syncthreads();
    float ro[16];
    {
        float acc[16], dk[16];
#pragma unroll
        for (int k = 0; k < 16; k++) { acc[k] = 3.0e38f; dk[k] = (float)(gq + 4 * k); }
        for (int j = 0; j < 64; j++) {
            const float fj = T[j * 64 + w];
#pragma unroll
            for (int k = 0; k < 16; k++) {
                acc[k] = fminf(acc[k], fmaf(dk[k], dk[k], fj));
                dk[k] -= 1.0f;
            }
        }
#pragma unroll
        for (int k = 0; k < 16; k++) ro[k] = acc[k];
    }
    __syncthreads();

    // ---- transform IN volume ----
#pragma unroll
    for (int r = 0; r < 16; r++) {
        int idx = tid + r * 256;
        T[idx] = g_F[baseI + (size_t)(idx >> 6) * 4096 + (idx & 63)];
    }
    __syncthreads();
    float local = 0.f;
    {
        float acc[16], dk[16];
#pragma unroll
        for (int k = 0; k < 16; k++) { acc[k] = 3.0e38f; dk[k] = (float)(gq + 4 * k); }
        for (int j = 0; j < 64; j++) {
            const float fj = T[j * 64 + w];
#pragma unroll
            for (int k = 0; k < 16; k++) {
                acc[k] = fminf(acc[k], fmaf(dk[k], dk[k], fj));
                dk[k] -= 1.0f;
            }
        }
#pragma unroll
        for (int k = 0; k < 16; k++) {
            const int dd = gq + 4 * k;
            const float sdf = sqrtf(ro[k]) - sqrtf(acc[k]);
            const float pr = g_prob[(size_t)p * SVOL + (size_t)dd * 4096 + (size_t)h * 64 + w];
            local = fmaf(sdf, pr, local);
        }
    }

    // block reduce
#pragma unroll
    for (int o = 16; o > 0; o >>= 1) local += __shfl_down_sync(0xFFFFFFFFu, local, o);
    const int wid = tid >> 5;
    if ((tid & 31) == 0) red[wid] = local;
    __syncthreads();
    if (tid == 0) {
        float sum = 0.f;
#pragma unroll
        for (int k = 0; k < 8; k++) sum += red[k];
        atomicAdd(&g_bsum[p], sum);
    }
}

// ============================================================
// K4: assemble scalar loss
// ============================================================
__global__ void k4_final(float* out) {
    if (threadIdx.x == 0) {
        float dice = 0.f;
        for (int bc = 0; bc < 16; bc++) {
            const float TP = g_TP[bc], PS = g_PS[bc], CNT = g_CNT[bc];
            const float FP = PS - TP;
            const float FN = CNT - TP;
            dice += (TP + SMOOTHV) / (TP + 0.3f * FP + 0.7f * FN + SMOOTHV);
        }
        const float l_dice = 1.0f - dice / 16.0f;
        const float l_main = g_focal / (float)NTOT;

        float bacc = 0.f;
        for (int p = 0; p < NPAIR; p++) {
            const int b = p / 3, c = p % 3 + 1;
            const float cnt = g_CNT[b * 4 + c];
            if (cnt > 0.f) {
                float contrib;
                if (cnt >= (float)SVOL)
                    contrib = -g_PS[b * 4 + c] / (float)SVOL;   // sdf == -1 everywhere
                else
                    contrib = g_bsum[p] / (float)SVOL;
                bacc += contrib;
            }
        }
        const float l_bound = bacc / (12.0f + 1e-8f);
        out[0] = l_dice + l_main + 0.01f * l_bound;
    }
}

extern "C" void kernel_launch(void* const* d_in, const int* in_sizes, int n_in,
                              void* d_out, int out_size) {
    const float* preds = (const float*)d_in[0];
    const int*   tgt   = (const int*)d_in[1];    // int32 view; int64 detected at runtime
    (void)in_sizes; (void)n_in; (void)out_size;

    k0_init<<<1, 256>>>(tgt);
    k1_main<<<NTOT / 256, 256>>>(preds, tgt);
    k2_passH<<<NVOL * 64, 256>>>();
    k3_passD<<<NPAIR * 64, 256>>>();
    k4_final<<<1, 32>>>((float*)d_out);
}

// round 2
// speedup vs baseline: 1.3022x; 1.3022x over previous
#include <cuda_runtime.h>
#include <cstdint>

#define DIMS 64
#define SVOL (64*64*64)          // 262144 voxels per volume
#define NBATCH 4
#define NCLASS 4
#define NPAIR 12                 // B * (C-1)
#define NVOL 24                  // NPAIR * 2 (out/in seeds)
#define NTOT (NBATCH*SVOL)       // 1048576
#define INF_SENT 1e12f
#define SMOOTHV 1e-5f

// ---- scratch (static device globals; no runtime allocation) ----
__device__ float g_F [(size_t)NVOL * SVOL];     // pass-1 output (~25 MB)
__device__ float g_F2[(size_t)NVOL * SVOL];     // pass-2 output (~25 MB)
__device__ float g_prob[(size_t)NPAIR * SVOL];  // probs classes 1..3 (~12.6 MB)
__device__ float g_TP[16];
__device__ float g_PS[16];
__device__ float g_CNT[16];
__device__ float g_focal;
__device__ float g_bsum[NPAIR];
__device__ int   g_flag64;

// ============================================================
// K0: zero accumulators + detect whether targets buffer is int64
// ============================================================
__global__ void k0_init(const int* __restrict__ tgt32) {
    int t = threadIdx.x;
    __shared__ int any;
    if (t == 0) any = 0;
    __syncthreads();
    int v = tgt32[2 * t + 1];
    if (v != 0) atomicOr(&any, 1);
    __syncthreads();
    if (t == 0) g_flag64 = (any == 0) ? 1 : 0;
    if (t < 16) { g_TP[t] = 0.f; g_PS[t] = 0.f; g_CNT[t] = 0.f; }
    if (t < NPAIR) g_bsum[t] = 0.f;
    if (t == 0) g_focal = 0.f;
}

// nearest set-bit squared distance within a 64-bit line mask
__device__ __forceinline__ float nd2(unsigned long long M, int i) {
    if (M == 0ULL) return INF_SENT;
    unsigned long long L = M << (63 - i);
    int dl = L ? __clzll((long long)L) : 9999;
    unsigned long long R = M >> i;
    int dr = R ? (__ffsll((long long)R) - 1) : 9999;
    int d = min(dl, dr);
    return (float)(d * d);
}

// ============================================================
// K1: softmax, focal, Tversky partials, prob store, EDT pass-1 (W axis)
// ============================================================
__global__ void __launch_bounds__(256) k1_main(const float* __restrict__ preds,
                                               const int* __restrict__ tgt32) {
    const int tid = threadIdx.x;
    const int g = blockIdx.x * 256 + tid;
    const int b = g >> 18;
    const int s = g & (SVOL - 1);

    const int f64 = g_flag64;
    const int t = tgt32[f64 ? (g << 1) : g];

    const float x0 = preds[(size_t)(b * 4 + 0) * SVOL + s];
    const float x1 = preds[(size_t)(b * 4 + 1) * SVOL + s];
    const float x2 = preds[(size_t)(b * 4 + 2) * SVOL + s];
    const float x3 = preds[(size_t)(b * 4 + 3) * SVOL + s];

    const float m  = fmaxf(fmaxf(x0, x1), fmaxf(x2, x3));
    const float e0 = expf(x0 - m), e1 = expf(x1 - m);
    const float e2 = expf(x2 - m), e3 = expf(x3 - m);
    const float se = e0 + e1 + e2 + e3;
    const float inv = 1.0f / se;
    const float p0 = e0 * inv, p1 = e1 * inv, p2 = e2 * inv, p3 = e3 * inv;

    const float xt = (t == 0) ? x0 : (t == 1) ? x1 : (t == 2) ? x2 : x3;
    const float ce = -(xt - m - logf(se));
    const float pt = (t == 0) ? p0 : (t == 1) ? p1 : (t == 2) ? p2 : p3;
    const float om = 1.0f - pt;
    const float focal = om * om * ce;

    g_prob[(size_t)(b * 3 + 0) * SVOL + s] = p1;
    g_prob[(size_t)(b * 3 + 1) * SVOL + s] = p2;
    g_prob[(size_t)(b * 3 + 2) * SVOL + s] = p3;

    // ---- EDT pass-1 along W via line bitmasks ----
    const unsigned full = 0xFFFFFFFFu;
    const unsigned bal1 = __ballot_sync(full, t == 1);
    const unsigned bal2 = __ballot_sync(full, t == 2);
    const unsigned bal3 = __ballot_sync(full, t == 3);
    __shared__ unsigned sb[3][8];
    const int wid = tid >> 5;
    if ((tid & 31) == 0) { sb[0][wid] = bal1; sb[1][wid] = bal2; sb[2][wid] = bal3; }
    __syncthreads();

    const int line = tid >> 6;
    const int i = tid & 63;
#pragma unroll
    for (int cm = 0; cm < 3; cm++) {
        unsigned long long M = (unsigned long long)sb[cm][line * 2] |
                               ((unsigned long long)sb[cm][line * 2 + 1] << 32);
        const int v = (b * 3 + cm) * 2;
        g_F[(size_t)v * SVOL + s]       = nd2(M, i);
        g_F[(size_t)(v + 1) * SVOL + s] = nd2(~M, i);
    }

    // ---- block reduce 13 quantities, then atomic ----
    float vals[13];
    vals[0] = (t == 0) ? p0 : 0.f;
    vals[1] = (t == 1) ? p1 : 0.f;
    vals[2] = (t == 2) ? p2 : 0.f;
    vals[3] = (t == 3) ? p3 : 0.f;
    vals[4] = p0; vals[5] = p1; vals[6] = p2; vals[7] = p3;
    vals[8]  = (t == 0) ? 1.f : 0.f;
    vals[9]  = (t == 1) ? 1.f : 0.f;
    vals[10] = (t == 2) ? 1.f : 0.f;
    vals[11] = (t == 3) ? 1.f : 0.f;
    vals[12] = focal;

    __shared__ float red[13 * 8];
#pragma unroll
    for (int q = 0; q < 13; q++) {
        float v = vals[q];
#pragma unroll
        for (int o = 16; o > 0; o >>= 1) v += __shfl_down_sync(full, v, o);
        if ((tid & 31) == 0) red[q * 8 + wid] = v;
    }
    __syncthreads();
    if (tid < 13) {
        float sum = 0.f;
#pragma unroll
        for (int k = 0; k < 8; k++) sum += red[tid * 8 + k];
        if (tid < 4)       atomicAdd(&g_TP[b * 4 + tid], sum);
        else if (tid < 8)  atomicAdd(&g_PS[b * 4 + tid - 4], sum);
        else if (tid < 12) atomicAdd(&g_CNT[b * 4 + tid - 8], sum);
        else               atomicAdd(&g_focal, sum);
    }
}

// ============================================================
// K2: EDT pass along H (g_F -> g_F2).
// 2 blocks per (volume, d) slice; thread owns column w and 8 rows.
// Inner loop: min_j (f[j]+j^2 - 2 i j), +i^2 at the end.
// ============================================================
__global__ void __launch_bounds__(256) k2_passH() {
    __shared__ __align__(16) float T[4096];
    const int slice = blockIdx.x >> 1;
    const int half  = blockIdx.x & 1;
    const int v = slice >> 6;
    const int d = slice & 63;
    const size_t base = (size_t)v * SVOL + (size_t)d * 4096;
    const int tid = threadIdx.x;

    // load slice (float4) and fold +j^2
    const float4* src = reinterpret_cast<const float4*>(g_F + base);
    float4* Tv = reinterpret_cast<float4*>(T);
#pragma unroll
    for (int r = 0; r < 4; r++) {
        int m = tid + r * 256;
        float4 val = src[m];
        float jv = (float)(m >> 4);
        float j2 = jv * jv;
        val.x += j2; val.y += j2; val.z += j2; val.w += j2;
        Tv[m] = val;
    }
    __syncthreads();

    const int w = tid & 63;
    const int gq = tid >> 6;
    const int ib = half * 32 + gq;     // rows ib + 4k, k<8
    float acc[8], ck[8];
#pragma unroll
    for (int k = 0; k < 8; k++) {
        acc[k] = 3.0e38f;
        ck[k] = -2.0f * (float)(ib + 4 * k);
    }

    float jf = 0.f;
    for (int j = 0; j < 64; j++, jf += 1.0f) {
        const float gj = T[j * 64 + w];
#pragma unroll
        for (int k = 0; k < 8; k++)
            acc[k] = fminf(acc[k], fmaf(ck[k], jf, gj));
    }
#pragma unroll
    for (int k = 0; k < 8; k++) {
        const int i = ib + 4 * k;
        g_F2[base + (size_t)i * 64 + w] = acc[k] + (float)(i * i);
    }
}

// ============================================================
// K3: EDT pass along D (reads g_F2) + sdf = sqrt(out)-sqrt(in),
//     contrib = sum(sdf * prob). 2 blocks per (pair, h); 8 rows/thread.
// ============================================================
__global__ void __launch_bounds__(256) k3_passD() {
    __shared__ __align__(16) float T[4096];
    __shared__ float red[8];
    const int p    = blockIdx.x >> 7;
    const int rem  = blockIdx.x & 127;
    const int h    = rem >> 1;
    const int half = rem & 1;
    const int tid = threadIdx.x;
    const int w = tid & 63;
    const int gq = tid >> 6;
    const int ib = half * 32 + gq;
    const size_t baseO = (size_t)(2 * p) * SVOL + (size_t)h * 64;
    const size_t baseI = baseO + SVOL;

    float ro[8];
    // ---- OUT volume ----
#pragma unroll
    for (int r = 0; r < 4; r++) {
        int m = tid + r * 256;           // float4 index; element = 4m
        int dd = m >> 4;                 // source row (d)
        int w0 = (4 * m) & 63;
        float4 val = *reinterpret_cast<const float4*>(&g_F2[baseO + (size_t)dd * 4096 + w0]);
        float jv = (float)dd, j2 = jv * jv;
        val.x += j2; val.y += j2; val.z += j2; val.w += j2;
        reinterpret_cast<float4*>(T)[m] = val;
    }
    __syncthreads();
    {
        float acc[8], ck[8];
#pragma unroll
        for (int k = 0; k < 8; k++) { acc[k] = 3.0e38f; ck[k] = -2.0f * (float)(ib + 4 * k); }
        float jf = 0.f;
        for (int j = 0; j < 64; j++, jf += 1.0f) {
            const float gj = T[j * 64 + w];
#pragma unroll
            for (int k = 0; k < 8; k++)
                acc[k] = fminf(acc[k], fmaf(ck[k], jf, gj));
        }
#pragma unroll
        for (int k = 0; k < 8; k++) {
            const int i = ib + 4 * k;
            ro[k] = acc[k] + (float)(i * i);
        }
    }
    __syncthreads();

    // ---- IN volume ----
#pragma unroll
    for (int r = 0; r < 4; r++) {
        int m = tid + r * 256;
        int dd = m >> 4;
        int w0 = (4 * m) & 63;
        float4 val = *reinterpret_cast<const float4*>(&g_F2[baseI + (size_t)dd * 4096 + w0]);
        float jv = (float)dd, j2 = jv * jv;
        val.x += j2; val.y += j2; val.z += j2; val.w += j2;
        reinterpret_cast<float4*>(T)[m] = val;
    }
    __syncthreads();
    float local = 0.f;
    {
        float acc[8], ck[8];
#pragma unroll
        for (int k = 0; k < 8; k++) { acc[k] = 3.0e38f; ck[k] = -2.0f * (float)(ib + 4 * k); }
        float jf = 0.f;
        for (int j = 0; j < 64; j++, jf += 1.0f) {
            const float gj = T[j * 64 + w];
#pragma unroll
            for (int k = 0; k < 8; k++)
                acc[k] = fminf(acc[k], fmaf(ck[k], jf, gj));
        }
#pragma unroll
        for (int k = 0; k < 8; k++) {
            const int i = ib + 4 * k;
            const float ri = acc[k] + (float)(i * i);
            const float sdf = sqrtf(ro[k]) - sqrtf(ri);
            const float pr = g_prob[(size_t)p * SVOL + (size_t)i * 4096 + (size_t)h * 64 + w];
            local = fmaf(sdf, pr, local);
        }
    }

    // block reduce
#pragma unroll
    for (int o = 16; o > 0; o >>= 1) local += __shfl_down_sync(0xFFFFFFFFu, local, o);
    const int wid = tid >> 5;
    if ((tid & 31) == 0) red[wid] = local;
    __syncthreads();
    if (tid == 0) {
        float sum = 0.f;
#pragma unroll
        for (int k = 0; k < 8; k++) sum += red[k];
        atomicAdd(&g_bsum[p], sum);
    }
}

// ============================================================
// K4: assemble scalar loss
// ============================================================
__global__ void k4_final(float* out) {
    if (threadIdx.x == 0) {
        float dice = 0.f;
        for (int bc = 0; bc < 16; bc++) {
            const float TP = g_TP[bc], PS = g_PS[bc], CNT = g_CNT[bc];
            const float FP = PS - TP;
            const float FN = CNT - TP;
            dice += (TP + SMOOTHV) / (TP + 0.3f * FP + 0.7f * FN + SMOOTHV);
        }
        const float l_dice = 1.0f - dice / 16.0f;
        const float l_main = g_focal / (float)NTOT;

        float bacc = 0.f;
        for (int p = 0; p < NPAIR; p++) {
            const int b = p / 3, c = p % 3 + 1;
            const float cnt = g_CNT[b * 4 + c];
            if (cnt > 0.f) {
                float contrib;
                if (cnt >= (float)SVOL)
                    contrib = -g_PS[b * 4 + c] / (float)SVOL;
                else
                    contrib = g_bsum[p] / (float)SVOL;
                bacc += contrib;
            }
        }
        const float l_bound = bacc / (12.0f + 1e-8f);
        out[0] = l_dice + l_main + 0.01f * l_bound;
    }
}

extern "C" void kernel_launch(void* const* d_in, const int* in_sizes, int n_in,
                              void* d_out, int out_size) {
    const float* preds = (const float*)d_in[0];
    const int*   tgt   = (const int*)d_in[1];
    (void)in_sizes; (void)n_in; (void)out_size;

    k0_init<<<1, 256>>>(tgt);
    k1_main<<<NTOT / 256, 256>>>(preds, tgt);
    k2_passH<<<NVOL * 128, 256>>>();
    k3_passD<<<NPAIR * 128, 256>>>();
    k4_final<<<1, 32>>>((float*)d_out);
}

// round 3
// speedup vs baseline: 1.3581x; 1.0429x over previous
#include <cuda_runtime.h>
#include <cstdint>

#define DIMS 64
#define SVOL (64*64*64)
#define NBATCH 4
#define NCLASS 4
#define NPAIR 12
#define NVOL 24
#define NTOT (NBATCH*SVOL)
#define INF_SENT 1e12f
#define SMOOTHV 1e-5f

__device__ float g_F [(size_t)NVOL * SVOL];
__device__ float g_F2[(size_t)NVOL * SVOL];
__device__ float g_prob[(size_t)NPAIR * SVOL];
__device__ float g_TP[16];
__device__ float g_PS[16];
__device__ float g_CNT[16];
__device__ float g_focal;
__device__ float g_bsum[NPAIR];
__device__ int   g_flag64;

__device__ __forceinline__ void cp_async16(uint32_t dst, const float* src) {
    asm volatile("cp.async.cg.shared.global [%0], [%1], 16;" :: "r"(dst), "l"(src));
}

// ============================================================
// K0
// ============================================================
__global__ void k0_init(const int* __restrict__ tgt32) {
    int t = threadIdx.x;
    __shared__ int any;
    if (t == 0) any = 0;
    __syncthreads();
    int v = tgt32[2 * t + 1];
    if (v != 0) atomicOr(&any, 1);
    __syncthreads();
    if (t == 0) g_flag64 = (any == 0) ? 1 : 0;
    if (t < 16) { g_TP[t] = 0.f; g_PS[t] = 0.f; g_CNT[t] = 0.f; }
    if (t < NPAIR) g_bsum[t] = 0.f;
    if (t == 0) g_focal = 0.f;
}

__device__ __forceinline__ float nd2(unsigned long long M, int i) {
    if (M == 0ULL) return INF_SENT;
    unsigned long long L = M << (63 - i);
    int dl = L ? __clzll((long long)L) : 9999;
    unsigned long long R = M >> i;
    int dr = R ? (__ffsll((long long)R) - 1) : 9999;
    int d = min(dl, dr);
    return (float)(d * d);
}

// ============================================================
// K1: softmax, focal, Tversky partials, prob store, EDT pass-1 (W)
// ============================================================
__global__ void __launch_bounds__(256) k1_main(const float* __restrict__ preds,
                                               const int* __restrict__ tgt32) {
    const int tid = threadIdx.x;
    const int g = blockIdx.x * 256 + tid;
    const int b = g >> 18;
    const int s = g & (SVOL - 1);

    const int f64 = g_flag64;
    const int t = tgt32[f64 ? (g << 1) : g];

    const float x0 = preds[(size_t)(b * 4 + 0) * SVOL + s];
    const float x1 = preds[(size_t)(b * 4 + 1) * SVOL + s];
    const float x2 = preds[(size_t)(b * 4 + 2) * SVOL + s];
    const float x3 = preds[(size_t)(b * 4 + 3) * SVOL + s];

    const float m  = fmaxf(fmaxf(x0, x1), fmaxf(x2, x3));
    const float e0 = expf(x0 - m), e1 = expf(x1 - m);
    const float e2 = expf(x2 - m), e3 = expf(x3 - m);
    const float se = e0 + e1 + e2 + e3;
    const float inv = 1.0f / se;
    const float p0 = e0 * inv, p1 = e1 * inv, p2 = e2 * inv, p3 = e3 * inv;

    const float xt = (t == 0) ? x0 : (t == 1) ? x1 : (t == 2) ? x2 : x3;
    const float ce = -(xt - m - logf(se));
    const float pt = (t == 0) ? p0 : (t == 1) ? p1 : (t == 2) ? p2 : p3;
    const float om = 1.0f - pt;
    const float focal = om * om * ce;

    g_prob[(size_t)(b * 3 + 0) * SVOL + s] = p1;
    g_prob[(size_t)(b * 3 + 1) * SVOL + s] = p2;
    g_prob[(size_t)(b * 3 + 2) * SVOL + s] = p3;

    const unsigned full = 0xFFFFFFFFu;
    const unsigned bal1 = __ballot_sync(full, t == 1);
    const unsigned bal2 = __ballot_sync(full, t == 2);
    const unsigned bal3 = __ballot_sync(full, t == 3);
    __shared__ unsigned sb[3][8];
    const int wid = tid >> 5;
    if ((tid & 31) == 0) { sb[0][wid] = bal1; sb[1][wid] = bal2; sb[2][wid] = bal3; }
    __syncthreads();

    const int line = tid >> 6;
    const int i = tid & 63;
#pragma unroll
    for (int cm = 0; cm < 3; cm++) {
        unsigned long long M = (unsigned long long)sb[cm][line * 2] |
                               ((unsigned long long)sb[cm][line * 2 + 1] << 32);
        const int v = (b * 3 + cm) * 2;
        g_F[(size_t)v * SVOL + s]       = nd2(M, i);
        g_F[(size_t)(v + 1) * SVOL + s] = nd2(~M, i);
    }

    float vals[13];
    vals[0] = (t == 0) ? p0 : 0.f;
    vals[1] = (t == 1) ? p1 : 0.f;
    vals[2] = (t == 2) ? p2 : 0.f;
    vals[3] = (t == 3) ? p3 : 0.f;
    vals[4] = p0; vals[5] = p1; vals[6] = p2; vals[7] = p3;
    vals[8]  = (t == 0) ? 1.f : 0.f;
    vals[9]  = (t == 1) ? 1.f : 0.f;
    vals[10] = (t == 2) ? 1.f : 0.f;
    vals[11] = (t == 3) ? 1.f : 0.f;
    vals[12] = focal;

    __shared__ float red[13 * 8];
#pragma unroll
    for (int q = 0; q < 13; q++) {
        float v = vals[q];
#pragma unroll
        for (int o = 16; o > 0; o >>= 1) v += __shfl_down_sync(full, v, o);
        if ((tid & 31) == 0) red[q * 8 + wid] = v;
    }
    __syncthreads();
    if (tid < 13) {
        float sum = 0.f;
#pragma unroll
        for (int k = 0; k < 8; k++) sum += red[tid * 8 + k];
        if (tid < 4)       atomicAdd(&g_TP[b * 4 + tid], sum);
        else if (tid < 8)  atomicAdd(&g_PS[b * 4 + tid - 4], sum);
        else if (tid < 12) atomicAdd(&g_CNT[b * 4 + tid - 8], sum);
        else               atomicAdd(&g_focal, sum);
    }
}

// ============================================================
// K2: EDT pass along H (g_F -> g_F2). 512 threads, 1 block/slice.
// ============================================================
__global__ void __launch_bounds__(512, 2) k2_passH() {
    __shared__ __align__(16) float T[4096];
    const int v = blockIdx.x >> 6;
    const int d = blockIdx.x & 63;
    const size_t base = (size_t)v * SVOL + (size_t)d * 4096;
    const int tid = threadIdx.x;

    const float4* src = reinterpret_cast<const float4*>(g_F + base);
    float4* Tv = reinterpret_cast<float4*>(T);
#pragma unroll
    for (int r = 0; r < 2; r++) {
        int m = tid + r * 512;
        float4 val = src[m];
        float jv = (float)(m >> 4);
        float j2 = jv * jv;
        val.x += j2; val.y += j2; val.z += j2; val.w += j2;
        Tv[m] = val;
    }
    __syncthreads();

    const int w = tid & 63;
    const int gq = tid >> 6;            // 0..7 ; rows i = gq + 8k
    float acc[8], ck[8];
#pragma unroll
    for (int k = 0; k < 8; k++) {
        acc[k] = 3.0e38f;
        ck[k] = -2.0f * (float)(gq + 8 * k);
    }

    float jf = 0.f;
#pragma unroll 4
    for (int j = 0; j < 64; j++, jf += 1.0f) {
        const float gj = T[j * 64 + w];
#pragma unroll
        for (int k = 0; k < 8; k++)
            acc[k] = fminf(acc[k], fmaf(ck[k], jf, gj));
    }
#pragma unroll
    for (int k = 0; k < 8; k++) {
        const int i = gq + 8 * k;
        g_F2[base + (size_t)i * 64 + w] = acc[k] + (float)(i * i);
    }
}

// ============================================================
// K3: EDT pass along D + sdf*prob reduction.
// cp.async prefetch of IN tile overlapped with OUT compute.
// ============================================================
__global__ void __launch_bounds__(256, 4) k3_passD() {
    __shared__ __align__(16) float To[4096];
    __shared__ __align__(16) float Ti[4096];
    __shared__ float red[8];
    const int p    = blockIdx.x >> 7;
    const int rem  = blockIdx.x & 127;
    const int h    = rem >> 1;
    const int half = rem & 1;
    const int tid = threadIdx.x;
    const int w = tid & 63;
    const int gq = tid >> 6;
    const int ib = half * 32 + gq;
    const size_t baseO = (size_t)(2 * p) * SVOL + (size_t)h * 64;
    const size_t baseI = baseO + SVOL;

    // ---- prefetch IN tile (raw) via cp.async ----
    const uint32_t tib = (uint32_t)__cvta_generic_to_shared(Ti);
#pragma unroll
    for (int r = 0; r < 4; r++) {
        int m = tid + r * 256;
        int dd = m >> 4;
        int w0 = (4 * m) & 63;
        cp_async16(tib + m * 16, &g_F2[baseI + (size_t)dd * 4096 + w0]);
    }
    asm volatile("cp.async.commit_group;");

    // ---- load OUT tile, fold +j^2 ----
#pragma unroll
    for (int r = 0; r < 4; r++) {
        int m = tid + r * 256;
        int dd = m >> 4;
        int w0 = (4 * m) & 63;
        float4 val = *reinterpret_cast<const float4*>(&g_F2[baseO + (size_t)dd * 4096 + w0]);
        float jv = (float)dd, j2 = jv * jv;
        val.x += j2; val.y += j2; val.z += j2; val.w += j2;
        reinterpret_cast<float4*>(To)[m] = val;
    }
    __syncthreads();

    float ro[8];
    {
        float acc[8], ck[8];
#pragma unroll
        for (int k = 0; k < 8; k++) { acc[k] = 3.0e38f; ck[k] = -2.0f * (float)(ib + 4 * k); }
        float jf = 0.f;
#pragma unroll 4
        for (int j = 0; j < 64; j++, jf += 1.0f) {
            const float gj = To[j * 64 + w];
#pragma unroll
            for (int k = 0; k < 8; k++)
                acc[k] = fminf(acc[k], fmaf(ck[k], jf, gj));
        }
#pragma unroll
        for (int k = 0; k < 8; k++) {
            const int i = ib + 4 * k;
            ro[k] = acc[k] + (float)(i * i);
        }
    }

    // ---- wait own cp.async, fold own IN elements (thread-local), barrier ----
    asm volatile("cp.async.wait_group 0;");
#pragma unroll
    for (int r = 0; r < 4; r++) {
        int m = tid + r * 256;
        float jv = (float)(m >> 4), j2 = jv * jv;
        float4 val = reinterpret_cast<float4*>(Ti)[m];
        val.x += j2; val.y += j2; val.z += j2; val.w += j2;
        reinterpret_cast<float4*>(Ti)[m] = val;
    }
    __syncthreads();

    float local = 0.f;
    {
        float acc[8], ck[8];
#pragma unroll
        for (int k = 0; k < 8; k++) { acc[k] = 3.0e38f; ck[k] = -2.0f * (float)(ib + 4 * k); }
        float jf = 0.f;
#pragma unroll 4
        for (int j = 0; j < 64; j++, jf += 1.0f) {
            const float gj = Ti[j * 64 + w];
#pragma unroll
            for (int k = 0; k < 8; k++)
                acc[k] = fminf(acc[k], fmaf(ck[k], jf, gj));
        }
#pragma unroll
        for (int k = 0; k < 8; k++) {
            const int i = ib + 4 * k;
            const float ri = acc[k] + (float)(i * i);
            const float sdf = sqrtf(ro[k]) - sqrtf(ri);
            const float pr = g_prob[(size_t)p * SVOL + (size_t)i * 4096 + (size_t)h * 64 + w];
            local = fmaf(sdf, pr, local);
        }
    }

#pragma unroll
    for (int o = 16; o > 0; o >>= 1) local += __shfl_down_sync(0xFFFFFFFFu, local, o);
    const int wid = tid >> 5;
    if ((tid & 31) == 0) red[wid] = local;
    __syncthreads();
    if (tid == 0) {
        float sum = 0.f;
#pragma unroll
        for (int k = 0; k < 8; k++) sum += red[k];
        atomicAdd(&g_bsum[p], sum);
    }
}

// ============================================================
// K4
// ============================================================
__global__ void k4_final(float* out) {
    if (threadIdx.x == 0) {
        float dice = 0.f;
        for (int bc = 0; bc < 16; bc++) {
            const float TP = g_TP[bc], PS = g_PS[bc], CNT = g_CNT[bc];
            const float FP = PS - TP;
            const float FN = CNT - TP;
            dice += (TP + SMOOTHV) / (TP + 0.3f * FP + 0.7f * FN + SMOOTHV);
        }
        const float l_dice = 1.0f - dice / 16.0f;
        const float l_main = g_focal / (float)NTOT;

        float bacc = 0.f;
        for (int p = 0; p < NPAIR; p++) {
            const int b = p / 3, c = p % 3 + 1;
            const float cnt = g_CNT[b * 4 + c];
            if (cnt > 0.f) {
                float contrib;
                if (cnt >= (float)SVOL)
                    contrib = -g_PS[b * 4 + c] / (float)SVOL;
                else
                    contrib = g_bsum[p] / (float)SVOL;
                bacc += contrib;
            }
        }
        const float l_bound = bacc / (12.0f + 1e-8f);
        out[0] = l_dice + l_main + 0.01f * l_bound;
    }
}

extern "C" void kernel_launch(void* const* d_in, const int* in_sizes, int n_in,
                              void* d_out, int out_size) {
    const float* preds = (const float*)d_in[0];
    const int*   tgt   = (const int*)d_in[1];
    (void)in_sizes; (void)n_in; (void)out_size;

    k0_init<<<1, 256>>>(tgt);
    k1_main<<<NTOT / 256, 256>>>(preds, tgt);
    k2_passH<<<NVOL * 64, 512>>>();
    k3_passD<<<NPAIR * 128, 256>>>();
    k4_final<<<1, 32>>>((float*)d_out);
}